// round 13
// baseline (speedup 1.0000x reference)
#include <cuda_runtime.h>
#include <cuda_fp16.h>
#include <math.h>
#include <stdint.h>

#define T_  2048
#define B_  2
#define D_  1024
#define H_  16
#define HD  64
#define ROWS (T_*B_)   // 4096
#define BH  (B_*H_)    // 32
#define NT  (T_/64)    // 32 (64-col score tiles)
#define NQT (T_/128)   // 16 (128-row q blocks)
#define SCALING 0.125f
#define QSCALE  (0.125f * 1.4426950408889634f)   // fold log2(e) into q

// ---------------- scratch (static device globals) ---------------------------
__device__ __half g_x [ROWS * D_];
__device__ __half g_wq[D_ * D_], g_wk[D_ * D_], g_wv[D_ * D_], g_wo[D_ * D_];
__device__ __half g_qh[BH * T_ * HD];          // [bh][t][d]  (q pre-scaled by QSCALE)
__device__ __half g_kh[BH * T_ * HD];          // [bh][t][d]
__device__ __half g_vt[BH * HD * T_];          // [bh][d][t]
__device__ __half g_attn[ROWS * D_];
__device__ float  g_lse [BH * T_];             // base-2 lse
__device__ float  g_mloc[BH * T_ * NT];        // base-2 running max per s-tile
__device__ __half g_e[(size_t)BH * T_ * T_];

// ---------------- helpers ---------------------------------------------------
__device__ __forceinline__ uint32_t sptr(const void* p) {
    return (uint32_t)__cvta_generic_to_shared(p);
}

__device__ __forceinline__ void cp16(const void* dst_smem, const void* src) {
    uint32_t d = (uint32_t)__cvta_generic_to_shared(dst_smem);
    asm volatile("cp.async.cg.shared.global [%0], [%1], 16;" :: "r"(d), "l"(src));
}
#define CP_COMMIT() asm volatile("cp.async.commit_group;")
template<int N> __device__ __forceinline__ void cp_wait() {
    asm volatile("cp.async.wait_group %0;" :: "n"(N));
}

__device__ __forceinline__ void mma16(float c[4], const unsigned a[4], const unsigned b[2]) {
    asm volatile(
        "mma.sync.aligned.m16n8k16.row.col.f32.f16.f16.f32 "
        "{%0,%1,%2,%3},{%4,%5,%6,%7},{%8,%9},{%0,%1,%2,%3};"
        : "+f"(c[0]), "+f"(c[1]), "+f"(c[2]), "+f"(c[3])
        : "r"(a[0]), "r"(a[1]), "r"(a[2]), "r"(a[3]), "r"(b[0]), "r"(b[1]));
}

__device__ __forceinline__ void ldm_x4(unsigned r[4], uint32_t addr) {
    asm volatile("ldmatrix.sync.aligned.m8n8.x4.shared.b16 {%0,%1,%2,%3}, [%4];"
        : "=r"(r[0]), "=r"(r[1]), "=r"(r[2]), "=r"(r[3]) : "r"(addr));
}

// 2^x for x <= ~0, FMA-pipe only (no MUFU). Input already in log2 domain.
__device__ __forceinline__ float fast_exp2(float x) {
    x = fmaxf(x, -100.0f);
    float t = x + 12582912.0f;                  // round-to-nearest-int magic
    int   i = __float_as_int(t) - 0x4B400000;
    float f = x - (t - 12582912.0f);            // f in [-0.5, 0.5]
    float p = 1.3333558146e-3f;
    p = fmaf(p, f, 9.6181291076e-3f);
    p = fmaf(p, f, 5.5504108664e-2f);
    p = fmaf(p, f, 2.4022650696e-1f);
    p = fmaf(p, f, 6.9314718056e-1f);
    p = fmaf(p, f, 1.0f);
    return __int_as_float(__float_as_int(p) + (i << 23));
}

// ---------------------------------------------------------------------------
// Prep kernels: fp16-convert (wo split off so it can run on the side stream)
// ---------------------------------------------------------------------------
__global__ __launch_bounds__(256) void prep_main(
    const float* __restrict__ q,  const float* __restrict__ wq,
    const float* __restrict__ wk, const float* __restrict__ wv)
{
    const size_t NX = (size_t)ROWS * D_ / 4;
    const size_t NW = (size_t)D_ * D_ / 4;
    size_t i = (size_t)blockIdx.x * 256 + threadIdx.x;
    const float* src; __half* dst; size_t off;
    if      (i < NX)        { src = q;  dst = g_x;  off = i; }
    else if (i < NX + NW)   { src = wq; dst = g_wq; off = i - NX; }
    else if (i < NX + 2*NW) { src = wk; dst = g_wk; off = i - NX - NW; }
    else                    { src = wv; dst = g_wv; off = i - NX - 2*NW; }
    float4 v = ((const float4*)src)[off];
    __half2 h0 = __floats2half2_rn(v.x, v.y);
    __half2 h1 = __floats2half2_rn(v.z, v.w);
    uint2 u = { *(unsigned*)&h0, *(unsigned*)&h1 };
    ((uint2*)dst)[off] = u;
}

__global__ __launch_bounds__(256) void prep_wo(const float* __restrict__ wo)
{
    size_t i = (size_t)blockIdx.x * 256 + threadIdx.x;
    float4 v = ((const float4*)wo)[i];
    __half2 h0 = __floats2half2_rn(v.x, v.y);
    __half2 h1 = __floats2half2_rn(v.z, v.w);
    uint2 u = { *(unsigned*)&h0, *(unsigned*)&h1 };
    ((uint2*)g_wo)[i] = u;
}

// Zero-fill the strictly-upper-triangle tiles of the avg-weights output.
__global__ __launch_bounds__(256) void zfill_kernel(float* __restrict__ out)
{
    int st = blockIdx.x, tt = blockIdx.y, b = blockIdx.z;
    if (st <= tt) return;
    int tid = threadIdx.x;
    int row = tid >> 2, cseg = (tid & 3) * 16;
    float* dst = out + (size_t)ROWS * D_ + (size_t)b * T_ * T_;
    float4* pout = (float4*)(dst + (size_t)(tt * 64 + row) * T_ + st * 64 + cseg);
    float4 z = {0.f, 0.f, 0.f, 0.f};
    pout[0] = z; pout[1] = z; pout[2] = z; pout[3] = z;
}

// ---------------------------------------------------------------------------
// GEMM (fp16 m16n8k16 + ldmatrix, cp.async 3-stage single-sync, BK=64).
// Dyn smem: 3 stages x 36,864 B = 110,592 B. 2 CTAs/SM.
// ---------------------------------------------------------------------------
extern __shared__ __half dynh[];

__device__ __forceinline__ void gemm_load_stage(
    __half* buf, const __half* Ain, const __half* W,
    int m0, int n0, int k0, int tid)
{
    #pragma unroll
    for (int p = 0; p < 8; p++) {
        int i = p * 256 + tid;            // 0..2047 chunks of 8 halfs
        int which = i >> 10;              // 0 = A, 1 = W
        int j = i & 1023;
        int row = j >> 3, c = (j & 7) * 8;
        const __half* src = which
            ? (W   + (size_t)(n0 + row) * D_ + k0 + c)
            : (Ain + (size_t)(m0 + row) * D_ + k0 + c);
        cp16(buf + which * 9216 + row * 72 + c, src);
    }
    CP_COMMIT();
}

__global__ __launch_bounds__(256, 2) void gemm_fp16(
    const float* __restrict__ Bi0, const float* __restrict__ Bi1,
    const float* __restrict__ Bi2, float* __restrict__ C, int modeSel)
{
    int mode = (modeSel < 0) ? (int)blockIdx.z : modeSel;
    const __half* W    = (mode == 1) ? g_wk : (mode == 2) ? g_wv : (mode == 3) ? g_wo : g_wq;
    const float* bias  = (mode == 1) ? Bi1 : (mode == 2) ? Bi2 : Bi0;
    const __half* Ain  = (mode == 3) ? g_attn : g_x;

    int m0 = blockIdx.y * 128;
    int n0 = blockIdx.x * 128;
    int tid = threadIdx.x, lane = tid & 31, warp = tid >> 5;
    int mw = warp >> 1, nw = warp & 1;
    int gid = lane >> 2, tig = lane & 3;

    int a_row = lane & 15;
    int a_col = ((lane >> 4) & 1) * 8;
    int b_row = ((lane >> 4) & 1) * 8 + (lane & 7);
    int b_col = ((lane >> 3) & 1) * 8;

    float acc[2][8][4] = {};

    gemm_load_stage(dynh,         Ain, W, m0, n0, 0,  tid);
    gemm_load_stage(dynh + 18432, Ain, W, m0, n0, 64, tid);

    for (int kt = 0; kt < 16; kt++) {            // BK = 64
        if (kt + 1 < 16) cp_wait<1>(); else cp_wait<0>();
        __syncthreads();                          // stage kt ready; all warps past compute kt-1
        if (kt + 2 < 16)
            gemm_load_stage(dynh + ((kt + 2) % 3) * 18432, Ain, W, m0, n0, (kt + 2) * 64, tid);

        __half* AsS = dynh + (kt % 3) * 18432;
        __half* WsS = AsS + 9216;

        #pragma unroll
        for (int kc = 0; kc < 4; kc++) {
            unsigned af[2][4];
            #pragma unroll
            for (int mi = 0; mi < 2; mi++) {
                int r = mw * 32 + mi * 16 + a_row;
                ldm_x4(af[mi], sptr(&AsS[r * 72 + kc * 16 + a_col]));
            }
            #pragma unroll
            for (int jb = 0; jb < 4; jb++) {
                unsigned rr[4];
                int n = nw * 64 + jb * 16 + b_row;
                ldm_x4(rr, sptr(&WsS[n * 72 + kc * 16 + b_col]));
                mma16(acc[0][2 * jb],     af[0], rr);
                mma16(acc[1][2 * jb],     af[1], rr);
                mma16(acc[0][2 * jb + 1], af[0], rr + 2);
                mma16(acc[1][2 * jb + 1], af[1], rr + 2);
            }
        }
    }

    #pragma unroll
    for (int mi = 0; mi < 2; mi++) {
        int r = m0 + mw * 32 + mi * 16 + gid;
        #pragma unroll
        for (int j = 0; j < 8; j++) {
            int c = n0 + nw * 64 + j * 8 + tig * 2;
            float b0v = bias[c], b1v = bias[c + 1];
            float2 v0 = { acc[mi][j][0] + b0v, acc[mi][j][1] + b1v };
            float2 v1 = { acc[mi][j][2] + b0v, acc[mi][j][3] + b1v };
            if (mode == 0) { v0.x *= QSCALE; v0.y *= QSCALE; v1.x *= QSCALE; v1.y *= QSCALE; }
            if (mode == 3) {
                *(float2*)&C[(size_t)r * D_ + c] = v0;
                *(float2*)&C[(size_t)(r + 8) * D_ + c] = v1;
            } else if (mode == 2) {
                int h = c >> 6, d = c & 63;
                int t = r >> 1, b = r & 1;
                size_t base = ((size_t)(b * H_ + h) * HD + d) * T_;
                g_vt[base + t]      = __float2half(v0.x);
                g_vt[base + T_ + t] = __float2half(v0.y);
                int t8 = t + 4;
                g_vt[base + t8]      = __float2half(v1.x);
                g_vt[base + T_ + t8] = __float2half(v1.y);
            } else {
                __half* outp = (mode == 0) ? g_qh : g_kh;
                int h = c >> 6, d = c & 63;
                int t = r >> 1, b = r & 1;
                __half2 h0 = __floats2half2_rn(v0.x, v0.y);
                __half2 h1 = __floats2half2_rn(v1.x, v1.y);
                *(__half2*)&outp[((size_t)(b * H_ + h) * T_ + t) * HD + d] = h0;
                *(__half2*)&outp[((size_t)(b * H_ + h) * T_ + t + 4) * HD + d] = h1;
            }
        }
    }
}

// ---------------------------------------------------------------------------
// Flash attention (fp16 m16n8k16 + ldmatrix, cp.async 3-stage single-sync).
// 2 CTAs/SM. Dyn smem: 3 stages x 18,432 B = 55,296 B.
// ---------------------------------------------------------------------------
__device__ __forceinline__ void flash_load_kv(
    __half* Kst, __half* Vst, const __half* kb, const __half* vtb, int s0, int tid)
{
    #pragma unroll
    for (int p = 0; p < 2; p++) {
        int i = p * 256 + tid;
        int row = i >> 3, c = (i & 7) * 8;
        cp16(Kst + row * 72 + c, kb  + (size_t)(s0 + row) * HD + c);
        cp16(Vst + row * 72 + c, vtb + (size_t)row * T_ + s0 + c);
    }
    CP_COMMIT();
}

__global__ __launch_bounds__(256, 2) void flash_fp16()
{
    int bh = blockIdx.y;
    int tt = (int)(gridDim.x - 1 - blockIdx.x);
    int t0 = tt * 128;
    int tid = threadIdx.x, lane = tid & 31, w = tid >> 5;
    int gid = lane >> 2, tig = lane & 3;
    int lrow = w * 16 + gid;

    int a_row = lane & 15;
    int a_col = ((lane >> 4) & 1) * 8;
    int b_row = ((lane >> 4) & 1) * 8 + (lane & 7);
    int b_col = ((lane >> 3) & 1) * 8;

    const __half* qb  = g_qh + (size_t)bh * T_ * HD;
    const __half* kb  = g_kh + (size_t)bh * T_ * HD;
    const __half* vtb = g_vt + (size_t)bh * HD * T_;

    // stage Q through smem (occupies stage-0 region; loads issued after sync)
    {
        #pragma unroll
        for (int p = 0; p < 4; p++) {
            int i = p * 256 + tid;
            int row = i >> 3, c = (i & 7) * 8;
            uint4 v = *(const uint4*)(qb + (size_t)(t0 + row) * HD + c);
            *(uint4*)(dynh + row * 72 + c) = v;
        }
    }
    __syncthreads();
    unsigned qf[4][4];
    {
        int r = w * 16 + a_row;
        #pragma unroll
        for (int kk = 0; kk < 4; kk++)
            ldm_x4(qf[kk], sptr(&dynh[r * 72 + kk * 16 + a_col]));
    }
    __syncthreads();

    float acc_o[8][4] = {};
    float m0v = -1e30f, m1v = -1e30f, l0 = 0.0f, l1 = 0.0f;

    int tt64 = tt * 2 + (lrow >= 64 ? 1 : 0);
    int rloc = lrow & 63;
    int nst = 2 * tt + 2;

    flash_load_kv(dynh, dynh + 4608, kb, vtb, 0, tid);
    if (nst > 1) flash_load_kv(dynh + 9216, dynh + 9216 + 4608, kb, vtb, 64, tid);

    for (int st = 0; st < nst; st++) {
        if (st + 1 < nst) cp_wait<1>(); else cp_wait<0>();
        __syncthreads();                          // stage st ready; all warps past st-1
        if (st + 2 < nst) {
            __half* Kn = dynh + ((st + 2) % 3) * 9216;
            flash_load_kv(Kn, Kn + 4608, kb, vtb, (st + 2) * 64, tid);
        }

        __half* Ks = dynh + (st % 3) * 9216;
        __half* Vs = Ks + 4608;

        float sc[8][4] = {};
        #pragma unroll
        for (int kk = 0; kk < 4; kk++) {
            #pragma unroll
            for (int jb = 0; jb < 4; jb++) {
                unsigned rr[4];
                int n = jb * 16 + b_row;
                ldm_x4(rr, sptr(&Ks[n * 72 + kk * 16 + b_col]));
                mma16(sc[2 * jb],     qf[kk], rr);
                mma16(sc[2 * jb + 1], qf[kk], rr + 2);
            }
        }

        if (st >= 2 * tt) {
            int s0 = st * 64;
            int rg0 = t0 + lrow, rg1 = rg0 + 8;
            #pragma unroll
            for (int j = 0; j < 8; j++) {
                int cg = s0 + j * 8 + 2 * tig;
                if (cg     > rg0) sc[j][0] = -1e30f;
                if (cg + 1 > rg0) sc[j][1] = -1e30f;
                if (cg     > rg1) sc[j][2] = -1e30f;
                if (cg + 1 > rg1) sc[j][3] = -1e30f;
            }
        }

        float mx0 = -1e30f, mx1 = -1e30f;
        #pragma unroll
        for (int j = 0; j < 8; j++) {
            mx0 = fmaxf(mx0, fmaxf(sc[j][0], sc[j][1]));
            mx1 = fmaxf(mx1, fmaxf(sc[j][2], sc[j][3]));
        }
        mx0 = fmaxf(mx0, __shfl_xor_sync(0xffffffffu, mx0, 1));
        mx0 = fmaxf(mx0, __shfl_xor_sync(0xffffffffu, mx0, 2));
        mx1 = fmaxf(mx1, __shfl_xor_sync(0xffffffffu, mx1, 1));
        mx1 = fmaxf(mx1, __shfl_xor_sync(0xffffffffu, mx1, 2));

        float mn0 = fmaxf(m0v, mx0), mn1 = fmaxf(m1v, mx1);
        float fac0 = fast_exp2(m0v - mn0), fac1 = fast_exp2(m1v - mn1);

        float s0v = 0.0f, s1v = 0.0f;
        #pragma unroll
        for (int j = 0; j < 8; j++) {
            sc[j][0] = fast_exp2(sc[j][0] - mn0);
            sc[j][1] = fast_exp2(sc[j][1] - mn0);
            sc[j][2] = fast_exp2(sc[j][2] - mn1);
            sc[j][3] = fast_exp2(sc[j][3] - mn1);
            s0v += sc[j][0] + sc[j][1];
            s1v += sc[j][2] + sc[j][3];
        }
        s0v += __shfl_xor_sync(0xffffffffu, s0v, 1);
        s0v += __shfl_xor_sync(0xffffffffu, s0v, 2);
        s1v += __shfl_xor_sync(0xffffffffu, s1v, 1);
        s1v += __shfl_xor_sync(0xffffffffu, s1v, 2);

        l0 = l0 * fac0 + s0v;
        l1 = l1 * fac1 + s1v;
        m0v = mn0; m1v = mn1;

        #pragma unroll
        for (int j = 0; j < 8; j++) {
            acc_o[j][0] *= fac0; acc_o[j][1] *= fac0;
            acc_o[j][2] *= fac1; acc_o[j][3] *= fac1;
        }

        unsigned p0[8], p1[8];
        #pragma unroll
        for (int j = 0; j < 8; j++) {
            __half2 a = __floats2half2_rn(sc[j][0], sc[j][1]);
            __half2 b2 = __floats2half2_rn(sc[j][2], sc[j][3]);
            p0[j] = *(unsigned*)&a;
            p1[j] = *(unsigned*)&b2;
        }

        __half* tb = g_e + ((size_t)(bh * NT + tt64) * NT + st) * 4096;
        #pragma unroll
        for (int j = 0; j < 8; j++) {
            int c = j * 8 + 2 * tig;
            *(unsigned*)(tb + rloc * 64 + c)       = p0[j];
            *(unsigned*)(tb + (rloc + 8) * 64 + c) = p1[j];
        }
        if (tig == 0) {
            g_mloc[((size_t)bh * T_ + t0 + lrow) * NT + st]     = mn0;
            g_mloc[((size_t)bh * T_ + t0 + lrow + 8) * NT + st] = mn1;
        }

        #pragma unroll
        for (int kk = 0; kk < 4; kk++) {
            unsigned af[4] = { p0[2 * kk], p1[2 * kk], p0[2 * kk + 1], p1[2 * kk + 1] };
            #pragma unroll
            for (int jb = 0; jb < 4; jb++) {
                unsigned rr[4];
                int n = jb * 16 + b_row;
                ldm_x4(rr, sptr(&Vs[n * 72 + kk * 16 + b_col]));
                mma16(acc_o[2 * jb],     af, rr);
                mma16(acc_o[2 * jb + 1], af, rr + 2);
            }
        }
    }

    int b = bh >> 4, h = bh & 15;
    float inv0 = 1.0f / l0, inv1 = 1.0f / l1;
    #pragma unroll
    for (int j = 0; j < 8; j++) {
        int d = h * 64 + j * 8 + 2 * tig;
        __half2 h0 = __floats2half2_rn(acc_o[j][0] * inv0, acc_o[j][1] * inv0);
        __half2 h1 = __floats2half2_rn(acc_o[j][2] * inv1, acc_o[j][3] * inv1);
        *(__half2*)&g_attn[((size_t)(t0 + lrow) * B_ + b) * D_ + d] = h0;
        *(__half2*)&g_attn[((size_t)(t0 + lrow + 8) * B_ + b) * D_ + d] = h1;
    }
    if (tig == 0) {
        g_lse[(size_t)bh * T_ + t0 + lrow]     = m0v + log2f(l0);
        g_lse[(size_t)bh * T_ + t0 + lrow + 8] = m1v + log2f(l1);
    }
}

// ---------------------------------------------------------------------------
// Avg weights: one-sync sfac precompute, sync-free streamed h-loop.
// Upper-triangle tiles are handled by zfill_kernel (early return here).
// ---------------------------------------------------------------------------
__global__ __launch_bounds__(256) void avg_kernel(float* __restrict__ out)
{
    __shared__ float sfac[16][64];
    int st = blockIdx.x, tt = blockIdx.y, b = blockIdx.z;
    if (st > tt) return;   // zero-filled by zfill_kernel

    int t0 = tt * 64, s0 = st * 64;
    int tid = threadIdx.x;
    int row = tid >> 2, cseg = (tid & 3) * 16;

    float* dst = out + (size_t)ROWS * D_ + (size_t)b * T_ * T_;
    float4* pout = (float4*)(dst + (size_t)(t0 + row) * T_ + s0 + cseg);

    #pragma unroll
    for (int q = 0; q < 4; q++) {
        int idx = tid * 4 + q;
        int h = idx >> 6, r = idx & 63;
        size_t rowg = (size_t)(b * H_ + h) * T_ + t0 + r;
        sfac[h][r] = fast_exp2(g_mloc[rowg * NT + st] - g_lse[rowg]);
    }
    __syncthreads();

    float acc[16] = {};
    const __half* ebase = g_e + ((size_t)(b * H_) * NT + tt) * NT * 4096
                          + (size_t)st * 4096 + row * 64 + cseg;
    #pragma unroll 4
    for (int h = 0; h < H_; h++) {
        float fac = sfac[h][row];
        const uint4* ep = (const uint4*)(ebase + (size_t)h * NT * NT * 4096);
        #pragma unroll
        for (int q2 = 0; q2 < 2; q2++) {
            uint4 u = ep[q2];
            const __half2* hp = (const __half2*)&u;
            #pragma unroll
            for (int i = 0; i < 4; i++) {
                float2 f = __half22float2(hp[i]);
                acc[q2 * 8 + i * 2]     += fac * f.x;
                acc[q2 * 8 + i * 2 + 1] += fac * f.y;
            }
        }
    }
    const float invH = 1.0f / (float)H_;
    #pragma unroll
    for (int q2 = 0; q2 < 4; q2++) {
        float4 v = { acc[q2 * 4] * invH, acc[q2 * 4 + 1] * invH,
                     acc[q2 * 4 + 2] * invH, acc[q2 * 4 + 3] * invH };
        pout[q2] = v;
    }
}

// ---------------------------------------------------------------------------
extern "C" void kernel_launch(void* const* d_in, const int* in_sizes, int n_in,
                              void* d_out, int out_size)
{
    const float* query = (const float*)d_in[0];
    const float* qw = (const float*)d_in[1];
    const float* qb = (const float*)d_in[2];
    const float* kw = (const float*)d_in[3];
    const float* kb = (const float*)d_in[4];
    const float* vw = (const float*)d_in[5];
    const float* vb = (const float*)d_in[6];
    const float* ow = (const float*)d_in[7];
    const float* ob = (const float*)d_in[8];
    float* out = (float*)d_out;

    const int SM_G = 110592;   // gemm: 3 stages
    const int SM_F = 55296;    // flash: 3 stages
    cudaFuncSetAttribute(gemm_fp16, cudaFuncAttributeMaxDynamicSharedMemorySize, SM_G);
    cudaFuncSetAttribute(flash_fp16, cudaFuncAttributeMaxDynamicSharedMemorySize, SM_F);

    // one-time side-stream + events (no device memory)
    static cudaStream_t s2 = nullptr;
    static cudaEvent_t ev1 = nullptr, ev2 = nullptr, evFork = nullptr, evJoin = nullptr;
    static bool init_ok = false;
    static bool init_tried = false;
    if (!init_tried) {
        init_tried = true;
        init_ok = (cudaStreamCreateWithFlags(&s2, cudaStreamNonBlocking) == cudaSuccess)
               && (cudaEventCreateWithFlags(&ev1, cudaEventDisableTiming) == cudaSuccess)
               && (cudaEventCreateWithFlags(&ev2, cudaEventDisableTiming) == cudaSuccess)
               && (cudaEventCreateWithFlags(&evFork, cudaEventDisableTiming) == cudaSuccess)
               && (cudaEventCreateWithFlags(&evJoin, cudaEventDisableTiming) == cudaSuccess);
    }

    const size_t NX = (size_t)ROWS * D_ / 4;
    const size_t NW = (size_t)D_ * D_ / 4;
    int prep_main_blocks = (int)((NX + 3 * NW) / 256);   // 7168
    int prep_wo_blocks   = (int)(NW / 256);              // 1024

    if (init_ok) {
        // main: prep_main -> proj(full) -> flash -> (wait wo) outproj
        // s2:   (wait prep_main) prep_wo -> zfill -> (wait flash) avg
        prep_main<<<prep_main_blocks, 256>>>(query, qw, kw, vw);
        cudaEventRecord(ev1, 0);
        cudaStreamWaitEvent(s2, ev1, 0);
        prep_wo<<<prep_wo_blocks, 256, 0, s2>>>(ow);
        zfill_kernel<<<dim3(NT, NT, B_), 256, 0, s2>>>(out);
        cudaEventRecord(ev2, s2);

        gemm_fp16<<<dim3(8, 32, 3), 256, SM_G>>>(qb, kb, vb, nullptr, -1);
        flash_fp16<<<dim3(NQT, BH), 256, SM_F>>>();

        cudaEventRecord(evFork, 0);
        cudaStreamWaitEvent(s2, evFork, 0);
        avg_kernel<<<dim3(NT, NT, B_), 256, 0, s2>>>(out);
        cudaStreamWaitEvent(0, ev2, 0);   // outproj needs g_wo ready
        gemm_fp16<<<dim3(8, 32, 1), 256, SM_G>>>(ob, ob, ob, out, 3);
        cudaEventRecord(evJoin, s2);
        cudaStreamWaitEvent(0, evJoin, 0);
    } else {
        prep_main<<<prep_main_blocks, 256>>>(query, qw, kw, vw);
        prep_wo<<<prep_wo_blocks, 256>>>(ow);
        zfill_kernel<<<dim3(NT, NT, B_), 256>>>(out);
        gemm_fp16<<<dim3(8, 32, 3), 256, SM_G>>>(qb, kb, vb, nullptr, -1);
        flash_fp16<<<dim3(NQT, BH), 256, SM_F>>>();
        avg_kernel<<<dim3(NT, NT, B_), 256>>>(out);
        gemm_fp16<<<dim3(8, 32, 1), 256, SM_G>>>(ob, ob, ob, out, 3);
    }
}

// round 14
// speedup vs baseline: 1.0045x; 1.0045x over previous
#include <cuda_runtime.h>
#include <cuda_fp16.h>
#include <math.h>
#include <stdint.h>

#define T_  2048
#define B_  2
#define D_  1024
#define H_  16
#define HD  64
#define ROWS (T_*B_)   // 4096
#define BH  (B_*H_)    // 32
#define NT  (T_/64)    // 32 (64-col score tiles)
#define NQT (T_/128)   // 16 (128-row q blocks)
#define SCALING 0.125f
#define QSCALE  (0.125f * 1.4426950408889634f)   // fold log2(e) into q

// ---------------- scratch (static device globals) ---------------------------
__device__ __half g_x [ROWS * D_];
__device__ __half g_wq[D_ * D_], g_wk[D_ * D_], g_wv[D_ * D_], g_wo[D_ * D_];
__device__ __half g_qh[BH * T_ * HD];          // [bh][t][d]  (q pre-scaled by QSCALE)
__device__ __half g_kh[BH * T_ * HD];          // [bh][t][d]
__device__ __half g_vt[BH * HD * T_];          // [bh][d][t]
__device__ __half g_attn[ROWS * D_];
__device__ float  g_lse [BH * T_];             // base-2 lse
__device__ float  g_mloc[BH * T_ * NT];        // base-2 running max per s-tile
__device__ __half g_e[(size_t)BH * T_ * T_];

// ---------------- helpers ---------------------------------------------------
__device__ __forceinline__ uint32_t sptr(const void* p) {
    return (uint32_t)__cvta_generic_to_shared(p);
}

__device__ __forceinline__ void cp16(const void* dst_smem, const void* src) {
    uint32_t d = (uint32_t)__cvta_generic_to_shared(dst_smem);
    asm volatile("cp.async.cg.shared.global [%0], [%1], 16;" :: "r"(d), "l"(src));
}
#define CP_COMMIT() asm volatile("cp.async.commit_group;")
template<int N> __device__ __forceinline__ void cp_wait() {
    asm volatile("cp.async.wait_group %0;" :: "n"(N));
}

__device__ __forceinline__ void mma16(float c[4], const unsigned a[4], const unsigned b[2]) {
    asm volatile(
        "mma.sync.aligned.m16n8k16.row.col.f32.f16.f16.f32 "
        "{%0,%1,%2,%3},{%4,%5,%6,%7},{%8,%9},{%0,%1,%2,%3};"
        : "+f"(c[0]), "+f"(c[1]), "+f"(c[2]), "+f"(c[3])
        : "r"(a[0]), "r"(a[1]), "r"(a[2]), "r"(a[3]), "r"(b[0]), "r"(b[1]));
}

__device__ __forceinline__ void ldm_x4(unsigned r[4], uint32_t addr) {
    asm volatile("ldmatrix.sync.aligned.m8n8.x4.shared.b16 {%0,%1,%2,%3}, [%4];"
        : "=r"(r[0]), "=r"(r[1]), "=r"(r[2]), "=r"(r[3]) : "r"(addr));
}

// 2^x for x <= ~0, FMA-pipe only (no MUFU). Input already in log2 domain.
__device__ __forceinline__ float fast_exp2(float x) {
    x = fmaxf(x, -100.0f);
    float t = x + 12582912.0f;                  // round-to-nearest-int magic
    int   i = __float_as_int(t) - 0x4B400000;
    float f = x - (t - 12582912.0f);            // f in [-0.5, 0.5]
    float p = 1.3333558146e-3f;
    p = fmaf(p, f, 9.6181291076e-3f);
    p = fmaf(p, f, 5.5504108664e-2f);
    p = fmaf(p, f, 2.4022650696e-1f);
    p = fmaf(p, f, 6.9314718056e-1f);
    p = fmaf(p, f, 1.0f);
    return __int_as_float(__float_as_int(p) + (i << 23));
}

// ---------------------------------------------------------------------------
// Prep kernels: fp16-convert (wo split off so it can run on the side stream)
// ---------------------------------------------------------------------------
__global__ __launch_bounds__(256) void prep_main(
    const float* __restrict__ q,  const float* __restrict__ wq,
    const float* __restrict__ wk, const float* __restrict__ wv)
{
    const size_t NX = (size_t)ROWS * D_ / 4;
    const size_t NW = (size_t)D_ * D_ / 4;
    size_t i = (size_t)blockIdx.x * 256 + threadIdx.x;
    const float* src; __half* dst; size_t off;
    if      (i < NX)        { src = q;  dst = g_x;  off = i; }
    else if (i < NX + NW)   { src = wq; dst = g_wq; off = i - NX; }
    else if (i < NX + 2*NW) { src = wk; dst = g_wk; off = i - NX - NW; }
    else                    { src = wv; dst = g_wv; off = i - NX - 2*NW; }
    float4 v = ((const float4*)src)[off];
    __half2 h0 = __floats2half2_rn(v.x, v.y);
    __half2 h1 = __floats2half2_rn(v.z, v.w);
    uint2 u = { *(unsigned*)&h0, *(unsigned*)&h1 };
    ((uint2*)dst)[off] = u;
}

__global__ __launch_bounds__(256) void prep_wo(const float* __restrict__ wo)
{
    size_t i = (size_t)blockIdx.x * 256 + threadIdx.x;
    float4 v = ((const float4*)wo)[i];
    __half2 h0 = __floats2half2_rn(v.x, v.y);
    __half2 h1 = __floats2half2_rn(v.z, v.w);
    uint2 u = { *(unsigned*)&h0, *(unsigned*)&h1 };
    ((uint2*)g_wo)[i] = u;
}

// Zero-fill the strictly-upper-triangle tiles of the avg-weights output.
__global__ __launch_bounds__(256) void zfill_kernel(float* __restrict__ out)
{
    int st = blockIdx.x, tt = blockIdx.y, b = blockIdx.z;
    if (st <= tt) return;
    int tid = threadIdx.x;
    int row = tid >> 2, cseg = (tid & 3) * 16;
    float* dst = out + (size_t)ROWS * D_ + (size_t)b * T_ * T_;
    float4* pout = (float4*)(dst + (size_t)(tt * 64 + row) * T_ + st * 64 + cseg);
    float4 z = {0.f, 0.f, 0.f, 0.f};
    pout[0] = z; pout[1] = z; pout[2] = z; pout[3] = z;
}

// ---------------------------------------------------------------------------
// GEMM (fp16 m16n8k16 + ldmatrix, cp.async 3-stage single-sync, BK=64).
// Dyn smem: 3 stages x 36,864 B = 110,592 B. 2 CTAs/SM.
// ---------------------------------------------------------------------------
extern __shared__ __half dynh[];

__device__ __forceinline__ void gemm_load_stage(
    __half* buf, const __half* Ain, const __half* W,
    int m0, int n0, int k0, int tid)
{
    #pragma unroll
    for (int p = 0; p < 8; p++) {
        int i = p * 256 + tid;            // 0..2047 chunks of 8 halfs
        int which = i >> 10;              // 0 = A, 1 = W
        int j = i & 1023;
        int row = j >> 3, c = (j & 7) * 8;
        const __half* src = which
            ? (W   + (size_t)(n0 + row) * D_ + k0 + c)
            : (Ain + (size_t)(m0 + row) * D_ + k0 + c);
        cp16(buf + which * 9216 + row * 72 + c, src);
    }
    CP_COMMIT();
}

__global__ __launch_bounds__(256, 2) void gemm_fp16(
    const float* __restrict__ Bi0, const float* __restrict__ Bi1,
    const float* __restrict__ Bi2, float* __restrict__ C, int modeSel)
{
    int mode = (modeSel < 0) ? (int)blockIdx.z : modeSel;
    const __half* W    = (mode == 1) ? g_wk : (mode == 2) ? g_wv : (mode == 3) ? g_wo : g_wq;
    const float* bias  = (mode == 1) ? Bi1 : (mode == 2) ? Bi2 : Bi0;
    const __half* Ain  = (mode == 3) ? g_attn : g_x;

    int m0 = blockIdx.y * 128;
    int n0 = blockIdx.x * 128;
    int tid = threadIdx.x, lane = tid & 31, warp = tid >> 5;
    int mw = warp >> 1, nw = warp & 1;
    int gid = lane >> 2, tig = lane & 3;

    int a_row = lane & 15;
    int a_col = ((lane >> 4) & 1) * 8;
    int b_row = ((lane >> 4) & 1) * 8 + (lane & 7);
    int b_col = ((lane >> 3) & 1) * 8;

    float acc[2][8][4] = {};

    gemm_load_stage(dynh,         Ain, W, m0, n0, 0,  tid);
    gemm_load_stage(dynh + 18432, Ain, W, m0, n0, 64, tid);

    for (int kt = 0; kt < 16; kt++) {            // BK = 64
        if (kt + 1 < 16) cp_wait<1>(); else cp_wait<0>();
        __syncthreads();
        if (kt + 2 < 16)
            gemm_load_stage(dynh + ((kt + 2) % 3) * 18432, Ain, W, m0, n0, (kt + 2) * 64, tid);

        __half* AsS = dynh + (kt % 3) * 18432;
        __half* WsS = AsS + 9216;

        #pragma unroll
        for (int kc = 0; kc < 4; kc++) {
            unsigned af[2][4];
            #pragma unroll
            for (int mi = 0; mi < 2; mi++) {
                int r = mw * 32 + mi * 16 + a_row;
                ldm_x4(af[mi], sptr(&AsS[r * 72 + kc * 16 + a_col]));
            }
            #pragma unroll
            for (int jb = 0; jb < 4; jb++) {
                unsigned rr[4];
                int n = nw * 64 + jb * 16 + b_row;
                ldm_x4(rr, sptr(&WsS[n * 72 + kc * 16 + b_col]));
                mma16(acc[0][2 * jb],     af[0], rr);
                mma16(acc[1][2 * jb],     af[1], rr);
                mma16(acc[0][2 * jb + 1], af[0], rr + 2);
                mma16(acc[1][2 * jb + 1], af[1], rr + 2);
            }
        }
    }

    #pragma unroll
    for (int mi = 0; mi < 2; mi++) {
        int r = m0 + mw * 32 + mi * 16 + gid;
        #pragma unroll
        for (int j = 0; j < 8; j++) {
            int c = n0 + nw * 64 + j * 8 + tig * 2;
            float b0v = bias[c], b1v = bias[c + 1];
            float2 v0 = { acc[mi][j][0] + b0v, acc[mi][j][1] + b1v };
            float2 v1 = { acc[mi][j][2] + b0v, acc[mi][j][3] + b1v };
            if (mode == 0) { v0.x *= QSCALE; v0.y *= QSCALE; v1.x *= QSCALE; v1.y *= QSCALE; }
            if (mode == 3) {
                *(float2*)&C[(size_t)r * D_ + c] = v0;
                *(float2*)&C[(size_t)(r + 8) * D_ + c] = v1;
            } else if (mode == 2) {
                int h = c >> 6, d = c & 63;
                int t = r >> 1, b = r & 1;
                size_t base = ((size_t)(b * H_ + h) * HD + d) * T_;
                g_vt[base + t]      = __float2half(v0.x);
                g_vt[base + T_ + t] = __float2half(v0.y);
                int t8 = t + 4;
                g_vt[base + t8]      = __float2half(v1.x);
                g_vt[base + T_ + t8] = __float2half(v1.y);
            } else {
                __half* outp = (mode == 0) ? g_qh : g_kh;
                int h = c >> 6, d = c & 63;
                int t = r >> 1, b = r & 1;
                __half2 h0 = __floats2half2_rn(v0.x, v0.y);
                __half2 h1 = __floats2half2_rn(v1.x, v1.y);
                *(__half2*)&outp[((size_t)(b * H_ + h) * T_ + t) * HD + d] = h0;
                *(__half2*)&outp[((size_t)(b * H_ + h) * T_ + t + 4) * HD + d] = h1;
            }
        }
    }
}

// ---------------------------------------------------------------------------
// Flash attention: deferred-PV pipeline. 4-stage K/V ring (prefetch dist 2),
// one sync/iter. PV(st-1) issues right after QK(st), overlapping softmax(st).
// Dyn smem: 4 x 18,432 = 73,728 B. 2 CTAs/SM.
// ---------------------------------------------------------------------------
__device__ __forceinline__ void flash_load_kv(
    __half* Kst, __half* Vst, const __half* kb, const __half* vtb, int s0, int tid)
{
    #pragma unroll
    for (int p = 0; p < 2; p++) {
        int i = p * 256 + tid;
        int row = i >> 3, c = (i & 7) * 8;
        cp16(Kst + row * 72 + c, kb  + (size_t)(s0 + row) * HD + c);
        cp16(Vst + row * 72 + c, vtb + (size_t)row * T_ + s0 + c);
    }
    CP_COMMIT();
}

__global__ __launch_bounds__(256, 2) void flash_fp16()
{
    int bh = blockIdx.y;
    int tt = (int)(gridDim.x - 1 - blockIdx.x);
    int t0 = tt * 128;
    int tid = threadIdx.x, lane = tid & 31, w = tid >> 5;
    int gid = lane >> 2, tig = lane & 3;
    int lrow = w * 16 + gid;

    int a_row = lane & 15;
    int a_col = ((lane >> 4) & 1) * 8;
    int b_row = ((lane >> 4) & 1) * 8 + (lane & 7);
    int b_col = ((lane >> 3) & 1) * 8;

    const __half* qb  = g_qh + (size_t)bh * T_ * HD;
    const __half* kb  = g_kh + (size_t)bh * T_ * HD;
    const __half* vtb = g_vt + (size_t)bh * HD * T_;

    // stage Q through smem (stage-0 region; K/V loads only issued after sync)
    {
        #pragma unroll
        for (int p = 0; p < 4; p++) {
            int i = p * 256 + tid;
            int row = i >> 3, c = (i & 7) * 8;
            uint4 v = *(const uint4*)(qb + (size_t)(t0 + row) * HD + c);
            *(uint4*)(dynh + row * 72 + c) = v;
        }
    }
    __syncthreads();
    unsigned qf[4][4];
    {
        int r = w * 16 + a_row;
        #pragma unroll
        for (int kk = 0; kk < 4; kk++)
            ldm_x4(qf[kk], sptr(&dynh[r * 72 + kk * 16 + a_col]));
    }
    __syncthreads();

    float acc_o[8][4] = {};
    float m0v = -1e30f, m1v = -1e30f, l0 = 0.0f, l1 = 0.0f;

    int tt64 = tt * 2 + (lrow >= 64 ? 1 : 0);
    int rloc = lrow & 63;
    int nst = 2 * tt + 2;

    // preload stages 0,1 (prefetch distance 2, ring of 4)
    flash_load_kv(dynh, dynh + 4608, kb, vtb, 0, tid);
    if (nst > 1) flash_load_kv(dynh + 9216, dynh + 9216 + 4608, kb, vtb, 64, tid);

    unsigned p0[8], p1[8];            // P fragments of previous s-tile

    for (int st = 0; st < nst; st++) {
        if (st + 1 < nst) cp_wait<1>(); else cp_wait<0>();
        __syncthreads();              // stage st ready; V(st-2)/K(st-1) fully consumed
        if (st + 2 < nst) {
            __half* Kn = dynh + ((st + 2) & 3) * 9216;
            flash_load_kv(Kn, Kn + 4608, kb, vtb, (st + 2) * 64, tid);
        }

        __half* Ks = dynh + (st & 3) * 9216;

        // ---- QK(st)
        float sc[8][4] = {};
        #pragma unroll
        for (int kk = 0; kk < 4; kk++) {
            #pragma unroll
            for (int jb = 0; jb < 4; jb++) {
                unsigned rr[4];
                int n = jb * 16 + b_row;
                ldm_x4(rr, sptr(&Ks[n * 72 + kk * 16 + b_col]));
                mma16(sc[2 * jb],     qf[kk], rr);
                mma16(sc[2 * jb + 1], qf[kk], rr + 2);
            }
        }

        // ---- deferred PV(st-1): overlaps the softmax below (independent regs)
        if (st > 0) {
            __half* Vp = dynh + ((st - 1) & 3) * 9216 + 4608;
            #pragma unroll
            for (int kk = 0; kk < 4; kk++) {
                unsigned af[4] = { p0[2 * kk], p1[2 * kk], p0[2 * kk + 1], p1[2 * kk + 1] };
                #pragma unroll
                for (int jb = 0; jb < 4; jb++) {
                    unsigned rr[4];
                    int n = jb * 16 + b_row;
                    ldm_x4(rr, sptr(&Vp[n * 72 + kk * 16 + b_col]));
                    mma16(acc_o[2 * jb],     af, rr);
                    mma16(acc_o[2 * jb + 1], af, rr + 2);
                }
            }
        }

        // ---- causal mask
        if (st >= 2 * tt) {
            int s0 = st * 64;
            int rg0 = t0 + lrow, rg1 = rg0 + 8;
            #pragma unroll
            for (int j = 0; j < 8; j++) {
                int cg = s0 + j * 8 + 2 * tig;
                if (cg     > rg0) sc[j][0] = -1e30f;
                if (cg + 1 > rg0) sc[j][1] = -1e30f;
                if (cg     > rg1) sc[j][2] = -1e30f;
                if (cg + 1 > rg1) sc[j][3] = -1e30f;
            }
        }

        // ---- online softmax (FMA pipe — overlaps PV HMMAs above)
        float mx0 = -1e30f, mx1 = -1e30f;
        #pragma unroll
        for (int j = 0; j < 8; j++) {
            mx0 = fmaxf(mx0, fmaxf(sc[j][0], sc[j][1]));
            mx1 = fmaxf(mx1, fmaxf(sc[j][2], sc[j][3]));
        }
        mx0 = fmaxf(mx0, __shfl_xor_sync(0xffffffffu, mx0, 1));
        mx0 = fmaxf(mx0, __shfl_xor_sync(0xffffffffu, mx0, 2));
        mx1 = fmaxf(mx1, __shfl_xor_sync(0xffffffffu, mx1, 1));
        mx1 = fmaxf(mx1, __shfl_xor_sync(0xffffffffu, mx1, 2));

        float mn0 = fmaxf(m0v, mx0), mn1 = fmaxf(m1v, mx1);
        float fac0 = fast_exp2(m0v - mn0), fac1 = fast_exp2(m1v - mn1);

        float s0v = 0.0f, s1v = 0.0f;
        #pragma unroll
        for (int j = 0; j < 8; j++) {
            sc[j][0] = fast_exp2(sc[j][0] - mn0);
            sc[j][1] = fast_exp2(sc[j][1] - mn0);
            sc[j][2] = fast_exp2(sc[j][2] - mn1);
            sc[j][3] = fast_exp2(sc[j][3] - mn1);
            s0v += sc[j][0] + sc[j][1];
            s1v += sc[j][2] + sc[j][3];
        }
        s0v += __shfl_xor_sync(0xffffffffu, s0v, 1);
        s0v += __shfl_xor_sync(0xffffffffu, s0v, 2);
        s1v += __shfl_xor_sync(0xffffffffu, s1v, 1);
        s1v += __shfl_xor_sync(0xffffffffu, s1v, 2);

        l0 = l0 * fac0 + s0v;
        l1 = l1 * fac1 + s1v;
        m0v = mn0; m1v = mn1;

        // ---- rescale acc (after PV(st-1) has accumulated)
        #pragma unroll
        for (int j = 0; j < 8; j++) {
            acc_o[j][0] *= fac0; acc_o[j][1] *= fac0;
            acc_o[j][2] *= fac1; acc_o[j][3] *= fac1;
        }

        // ---- pack P(st) (PV for it happens next iteration / after loop)
        #pragma unroll
        for (int j = 0; j < 8; j++) {
            __half2 a = __floats2half2_rn(sc[j][0], sc[j][1]);
            __half2 b2 = __floats2half2_rn(sc[j][2], sc[j][3]);
            p0[j] = *(unsigned*)&a;
            p1[j] = *(unsigned*)&b2;
        }

        __half* tb = g_e + ((size_t)(bh * NT + tt64) * NT + st) * 4096;
        #pragma unroll
        for (int j = 0; j < 8; j++) {
            int c = j * 8 + 2 * tig;
            *(unsigned*)(tb + rloc * 64 + c)       = p0[j];
            *(unsigned*)(tb + (rloc + 8) * 64 + c) = p1[j];
        }
        if (tig == 0) {
            g_mloc[((size_t)bh * T_ + t0 + lrow) * NT + st]     = mn0;
            g_mloc[((size_t)bh * T_ + t0 + lrow + 8) * NT + st] = mn1;
        }
    }

    // ---- tail PV(nst-1)
    {
        __half* Vp = dynh + ((nst - 1) & 3) * 9216 + 4608;
        #pragma unroll
        for (int kk = 0; kk < 4; kk++) {
            unsigned af[4] = { p0[2 * kk], p1[2 * kk], p0[2 * kk + 1], p1[2 * kk + 1] };
            #pragma unroll
            for (int jb = 0; jb < 4; jb++) {
                unsigned rr[4];
                int n = jb * 16 + b_row;
                ldm_x4(rr, sptr(&Vp[n * 72 + kk * 16 + b_col]));
                mma16(acc_o[2 * jb],     af, rr);
                mma16(acc_o[2 * jb + 1], af, rr + 2);
            }
        }
    }

    int b = bh >> 4, h = bh & 15;
    float inv0 = 1.0f / l0, inv1 = 1.0f / l1;
    #pragma unroll
    for (int j = 0; j < 8; j++) {
        int d = h * 64 + j * 8 + 2 * tig;
        __half2 h0 = __floats2half2_rn(acc_o[j][0] * inv0, acc_o[j][1] * inv0);
        __half2 h1 = __floats2half2_rn(acc_o[j][2] * inv1, acc_o[j][3] * inv1);
        *(__half2*)&g_attn[((size_t)(t0 + lrow) * B_ + b) * D_ + d] = h0;
        *(__half2*)&g_attn[((size_t)(t0 + lrow + 8) * B_ + b) * D_ + d] = h1;
    }
    if (tig == 0) {
        g_lse[(size_t)bh * T_ + t0 + lrow]     = m0v + log2f(l0);
        g_lse[(size_t)bh * T_ + t0 + lrow + 8] = m1v + log2f(l1);
    }
}

// ---------------------------------------------------------------------------
// Avg weights: one-sync sfac precompute, sync-free streamed h-loop.
// Upper-triangle tiles are handled by zfill_kernel (early return here).
// ---------------------------------------------------------------------------
__global__ __launch_bounds__(256) void avg_kernel(float* __restrict__ out)
{
    __shared__ float sfac[16][64];
    int st = blockIdx.x, tt = blockIdx.y, b = blockIdx.z;
    if (st > tt) return;   // zero-filled by zfill_kernel

    int t0 = tt * 64, s0 = st * 64;
    int tid = threadIdx.x;
    int row = tid >> 2, cseg = (tid & 3) * 16;

    float* dst = out + (size_t)ROWS * D_ + (size_t)b * T_ * T_;
    float4* pout = (float4*)(dst + (size_t)(t0 + row) * T_ + s0 + cseg);

    #pragma unroll
    for (int q = 0; q < 4; q++) {
        int idx = tid * 4 + q;
        int h = idx >> 6, r = idx & 63;
        size_t rowg = (size_t)(b * H_ + h) * T_ + t0 + r;
        sfac[h][r] = fast_exp2(g_mloc[rowg * NT + st] - g_lse[rowg]);
    }
    __syncthreads();

    float acc[16] = {};
    const __half* ebase = g_e + ((size_t)(b * H_) * NT + tt) * NT * 4096
                          + (size_t)st * 4096 + row * 64 + cseg;
    #pragma unroll 4
    for (int h = 0; h < H_; h++) {
        float fac = sfac[h][row];
        const uint4* ep = (const uint4*)(ebase + (size_t)h * NT * NT * 4096);
        #pragma unroll
        for (int q2 = 0; q2 < 2; q2++) {
            uint4 u = ep[q2];
            const __half2* hp = (const __half2*)&u;
            #pragma unroll
            for (int i = 0; i < 4; i++) {
                float2 f = __half22float2(hp[i]);
                acc[q2 * 8 + i * 2]     += fac * f.x;
                acc[q2 * 8 + i * 2 + 1] += fac * f.y;
            }
        }
    }
    const float invH = 1.0f / (float)H_;
    #pragma unroll
    for (int q2 = 0; q2 < 4; q2++) {
        float4 v = { acc[q2 * 4] * invH, acc[q2 * 4 + 1] * invH,
                     acc[q2 * 4 + 2] * invH, acc[q2 * 4 + 3] * invH };
        pout[q2] = v;
    }
}

// ---------------------------------------------------------------------------
extern "C" void kernel_launch(void* const* d_in, const int* in_sizes, int n_in,
                              void* d_out, int out_size)
{
    const float* query = (const float*)d_in[0];
    const float* qw = (const float*)d_in[1];
    const float* qb = (const float*)d_in[2];
    const float* kw = (const float*)d_in[3];
    const float* kb = (const float*)d_in[4];
    const float* vw = (const float*)d_in[5];
    const float* vb = (const float*)d_in[6];
    const float* ow = (const float*)d_in[7];
    const float* ob = (const float*)d_in[8];
    float* out = (float*)d_out;

    const int SM_G = 110592;   // gemm: 3 stages
    const int SM_F = 73728;    // flash: 4 stages
    cudaFuncSetAttribute(gemm_fp16, cudaFuncAttributeMaxDynamicSharedMemorySize, SM_G);
    cudaFuncSetAttribute(flash_fp16, cudaFuncAttributeMaxDynamicSharedMemorySize, SM_F);

    // one-time side-stream + events (no device memory)
    static cudaStream_t s2 = nullptr;
    static cudaEvent_t ev1 = nullptr, ev2 = nullptr, evFork = nullptr, evJoin = nullptr;
    static bool init_ok = false;
    static bool init_tried = false;
    if (!init_tried) {
        init_tried = true;
        init_ok = (cudaStreamCreateWithFlags(&s2, cudaStreamNonBlocking) == cudaSuccess)
               && (cudaEventCreateWithFlags(&ev1, cudaEventDisableTiming) == cudaSuccess)
               && (cudaEventCreateWithFlags(&ev2, cudaEventDisableTiming) == cudaSuccess)
               && (cudaEventCreateWithFlags(&evFork, cudaEventDisableTiming) == cudaSuccess)
               && (cudaEventCreateWithFlags(&evJoin, cudaEventDisableTiming) == cudaSuccess);
    }

    const size_t NX = (size_t)ROWS * D_ / 4;
    const size_t NW = (size_t)D_ * D_ / 4;
    int prep_main_blocks = (int)((NX + 3 * NW) / 256);   // 7168
    int prep_wo_blocks   = (int)(NW / 256);              // 1024

    if (init_ok) {
        // main: prep_main -> proj(full) -> flash -> (wait wo) outproj
        // s2:   (wait prep_main) prep_wo -> zfill -> (wait flash) avg
        prep_main<<<prep_main_blocks, 256>>>(query, qw, kw, vw);
        cudaEventRecord(ev1, 0);
        cudaStreamWaitEvent(s2, ev1, 0);
        prep_wo<<<prep_wo_blocks, 256, 0, s2>>>(ow);
        zfill_kernel<<<dim3(NT, NT, B_), 256, 0, s2>>>(out);
        cudaEventRecord(ev2, s2);

        gemm_fp16<<<dim3(8, 32, 3), 256, SM_G>>>(qb, kb, vb, nullptr, -1);
        flash_fp16<<<dim3(NQT, BH), 256, SM_F>>>();

        cudaEventRecord(evFork, 0);
        cudaStreamWaitEvent(s2, evFork, 0);
        avg_kernel<<<dim3(NT, NT, B_), 256, 0, s2>>>(out);
        cudaStreamWaitEvent(0, ev2, 0);   // outproj needs g_wo ready
        gemm_fp16<<<dim3(8, 32, 1), 256, SM_G>>>(ob, ob, ob, out, 3);
        cudaEventRecord(evJoin, s2);
        cudaStreamWaitEvent(0, evJoin, 0);
    } else {
        prep_main<<<prep_main_blocks, 256>>>(query, qw, kw, vw);
        prep_wo<<<prep_wo_blocks, 256>>>(ow);
        zfill_kernel<<<dim3(NT, NT, B_), 256>>>(out);
        gemm_fp16<<<dim3(8, 32, 3), 256, SM_G>>>(qb, kb, vb, nullptr, -1);
        flash_fp16<<<dim3(NQT, BH), 256, SM_F>>>();
        avg_kernel<<<dim3(NT, NT, B_), 256>>>(out);
        gemm_fp16<<<dim3(8, 32, 1), 256, SM_G>>>(ob, ob, ob, out, 3);
    }
}

// round 16
// speedup vs baseline: 1.0249x; 1.0203x over previous
#include <cuda_runtime.h>
#include <cuda_fp16.h>
#include <math.h>
#include <stdint.h>

#define T_  2048
#define B_  2
#define D_  1024
#define H_  16
#define HD  64
#define ROWS (T_*B_)   // 4096
#define BH  (B_*H_)    // 32
#define NT  (T_/64)    // 32 (64-col score tiles)
#define NQT (T_/128)   // 16 (128-row q blocks)
#define SCALING 0.125f
#define QSCALE  (0.125f * 1.4426950408889634f)   // fold log2(e) into q

// ---------------- scratch (static device globals) ---------------------------
__device__ __half g_x [ROWS * D_];
__device__ __half g_wq[D_ * D_], g_wk[D_ * D_], g_wv[D_ * D_], g_wo[D_ * D_];
__device__ __half g_qh[BH * T_ * HD];          // [bh][t][d]  (q pre-scaled by QSCALE)
__device__ __half g_kh[BH * T_ * HD];          // [bh][t][d]
__device__ __half g_vt[BH * HD * T_];          // [bh][d][t]
__device__ __half g_attn[ROWS * D_];
__device__ float  g_lse [BH * T_];             // base-2 lse
__device__ float  g_mloc[BH * T_ * NT];        // base-2 running max per s-tile
__device__ __half g_e[(size_t)BH * T_ * T_];

// ---------------- helpers ---------------------------------------------------
__device__ __forceinline__ uint32_t sptr(const void* p) {
    return (uint32_t)__cvta_generic_to_shared(p);
}

__device__ __forceinline__ void cp16(const void* dst_smem, const void* src) {
    uint32_t d = (uint32_t)__cvta_generic_to_shared(dst_smem);
    asm volatile("cp.async.cg.shared.global [%0], [%1], 16;" :: "r"(d), "l"(src));
}
#define CP_COMMIT() asm volatile("cp.async.commit_group;")
template<int N> __device__ __forceinline__ void cp_wait() {
    asm volatile("cp.async.wait_group %0;" :: "n"(N));
}

__device__ __forceinline__ void mma16(float c[4], const unsigned a[4], const unsigned b[2]) {
    asm volatile(
        "mma.sync.aligned.m16n8k16.row.col.f32.f16.f16.f32 "
        "{%0,%1,%2,%3},{%4,%5,%6,%7},{%8,%9},{%0,%1,%2,%3};"
        : "+f"(c[0]), "+f"(c[1]), "+f"(c[2]), "+f"(c[3])
        : "r"(a[0]), "r"(a[1]), "r"(a[2]), "r"(a[3]), "r"(b[0]), "r"(b[1]));
}

__device__ __forceinline__ void ldm_x4(unsigned r[4], uint32_t addr) {
    asm volatile("ldmatrix.sync.aligned.m8n8.x4.shared.b16 {%0,%1,%2,%3}, [%4];"
        : "=r"(r[0]), "=r"(r[1]), "=r"(r[2]), "=r"(r[3]) : "r"(addr));
}

// 2^x scalar (FMA-pipe poly) — used in epilogues / avg.
__device__ __forceinline__ float fast_exp2(float x) {
    x = fmaxf(x, -100.0f);
    float t = x + 12582912.0f;
    int   i = __float_as_int(t) - 0x4B400000;
    float f = x - (t - 12582912.0f);
    float p = 1.3333558146e-3f;
    p = fmaf(p, f, 9.6181291076e-3f);
    p = fmaf(p, f, 5.5504108664e-2f);
    p = fmaf(p, f, 2.4022650696e-1f);
    p = fmaf(p, f, 6.9314718056e-1f);
    p = fmaf(p, f, 1.0f);
    return __int_as_float(__float_as_int(p) + (i << 23));
}

// ---- packed f32x2 exp2: two clamped inputs (x,y in [-100, 0]) at once ------
// Order matters: k = (v+MAG)-MAG is exact; f = v-k is exact (Sterbenz).
__device__ __forceinline__ uint64_t dup2(float c) {
    uint32_t b = __float_as_uint(c);
    return ((uint64_t)b << 32) | b;
}

__device__ __forceinline__ void exp2_2(float& x, float& y) {
    const uint64_t MAG  = dup2(12582912.0f);
    const uint64_t NMAG = dup2(-12582912.0f);
    const uint64_t N1   = dup2(-1.0f);
    const uint64_t C5   = dup2(1.3333558146e-3f);
    const uint64_t C4   = dup2(9.6181291076e-3f);
    const uint64_t C3   = dup2(5.5504108664e-2f);
    const uint64_t C2   = dup2(2.4022650696e-1f);
    const uint64_t C1   = dup2(6.9314718056e-1f);
    const uint64_t C0   = dup2(1.0f);
    uint64_t v, t, k, f, p;
    asm("mov.b64 %0, {%1, %2};" : "=l"(v) : "f"(x), "f"(y));
    asm("add.rn.f32x2 %0, %1, %2;" : "=l"(t) : "l"(v), "l"(MAG));   // t = v + MAG (rounds)
    asm("add.rn.f32x2 %0, %1, %2;" : "=l"(k) : "l"(t), "l"(NMAG));  // k = t - MAG (exact int)
    asm("fma.rn.f32x2 %0, %1, %2, %3;" : "=l"(f) : "l"(k), "l"(N1), "l"(v)); // f = v - k (exact)
    asm("fma.rn.f32x2 %0, %1, %2, %3;" : "=l"(p) : "l"(C5), "l"(f), "l"(C4));
    asm("fma.rn.f32x2 %0, %1, %2, %3;" : "=l"(p) : "l"(p),  "l"(f), "l"(C3));
    asm("fma.rn.f32x2 %0, %1, %2, %3;" : "=l"(p) : "l"(p),  "l"(f), "l"(C2));
    asm("fma.rn.f32x2 %0, %1, %2, %3;" : "=l"(p) : "l"(p),  "l"(f), "l"(C1));
    asm("fma.rn.f32x2 %0, %1, %2, %3;" : "=l"(p) : "l"(p),  "l"(f), "l"(C0));
    uint32_t tl, th, pl, ph;
    asm("mov.b64 {%0, %1}, %2;" : "=r"(tl), "=r"(th) : "l"(t));
    asm("mov.b64 {%0, %1}, %2;" : "=r"(pl), "=r"(ph) : "l"(p));
    int il = (int)tl - 0x4B400000;
    int ih = (int)th - 0x4B400000;
    x = __int_as_float((int)pl + (il << 23));
    y = __int_as_float((int)ph + (ih << 23));
}

// ---------------------------------------------------------------------------
// Prep kernels
// ---------------------------------------------------------------------------
__global__ __launch_bounds__(256) void prep_main(
    const float* __restrict__ q,  const float* __restrict__ wq,
    const float* __restrict__ wk, const float* __restrict__ wv)
{
    const size_t NX = (size_t)ROWS * D_ / 4;
    const size_t NW = (size_t)D_ * D_ / 4;
    size_t i = (size_t)blockIdx.x * 256 + threadIdx.x;
    const float* src; __half* dst; size_t off;
    if      (i < NX)        { src = q;  dst = g_x;  off = i; }
    else if (i < NX + NW)   { src = wq; dst = g_wq; off = i - NX; }
    else if (i < NX + 2*NW) { src = wk; dst = g_wk; off = i - NX - NW; }
    else                    { src = wv; dst = g_wv; off = i - NX - 2*NW; }
    float4 v = ((const float4*)src)[off];
    __half2 h0 = __floats2half2_rn(v.x, v.y);
    __half2 h1 = __floats2half2_rn(v.z, v.w);
    uint2 u = { *(unsigned*)&h0, *(unsigned*)&h1 };
    ((uint2*)dst)[off] = u;
}

__global__ __launch_bounds__(256) void prep_wo(const float* __restrict__ wo)
{
    size_t i = (size_t)blockIdx.x * 256 + threadIdx.x;
    float4 v = ((const float4*)wo)[i];
    __half2 h0 = __floats2half2_rn(v.x, v.y);
    __half2 h1 = __floats2half2_rn(v.z, v.w);
    uint2 u = { *(unsigned*)&h0, *(unsigned*)&h1 };
    ((uint2*)g_wo)[i] = u;
}

__global__ __launch_bounds__(256) void zfill_kernel(float* __restrict__ out)
{
    int st = blockIdx.x, tt = blockIdx.y, b = blockIdx.z;
    if (st <= tt) return;
    int tid = threadIdx.x;
    int row = tid >> 2, cseg = (tid & 3) * 16;
    float* dst = out + (size_t)ROWS * D_ + (size_t)b * T_ * T_;
    float4* pout = (float4*)(dst + (size_t)(tt * 64 + row) * T_ + st * 64 + cseg);
    float4 z = {0.f, 0.f, 0.f, 0.f};
    pout[0] = z; pout[1] = z; pout[2] = z; pout[3] = z;
}

// ---------------------------------------------------------------------------
// GEMM (fp16 m16n8k16 + ldmatrix, cp.async 3-stage single-sync, BK=64).
// ---------------------------------------------------------------------------
extern __shared__ __half dynh[];

__device__ __forceinline__ void gemm_load_stage(
    __half* buf, const __half* Ain, const __half* W,
    int m0, int n0, int k0, int tid)
{
    #pragma unroll
    for (int p = 0; p < 8; p++) {
        int i = p * 256 + tid;
        int which = i >> 10;
        int j = i & 1023;
        int row = j >> 3, c = (j & 7) * 8;
        const __half* src = which
            ? (W   + (size_t)(n0 + row) * D_ + k0 + c)
            : (Ain + (size_t)(m0 + row) * D_ + k0 + c);
        cp16(buf + which * 9216 + row * 72 + c, src);
    }
    CP_COMMIT();
}

__global__ __launch_bounds__(256, 2) void gemm_fp16(
    const float* __restrict__ Bi0, const float* __restrict__ Bi1,
    const float* __restrict__ Bi2, float* __restrict__ C, int modeSel)
{
    int mode = (modeSel < 0) ? (int)blockIdx.z : modeSel;
    const __half* W    = (mode == 1) ? g_wk : (mode == 2) ? g_wv : (mode == 3) ? g_wo : g_wq;
    const float* bias  = (mode == 1) ? Bi1 : (mode == 2) ? Bi2 : Bi0;
    const __half* Ain  = (mode == 3) ? g_attn : g_x;

    int m0 = blockIdx.y * 128;
    int n0 = blockIdx.x * 128;
    int tid = threadIdx.x, lane = tid & 31, warp = tid >> 5;
    int mw = warp >> 1, nw = warp & 1;
    int gid = lane >> 2, tig = lane & 3;

    int a_row = lane & 15;
    int a_col = ((lane >> 4) & 1) * 8;
    int b_row = ((lane >> 4) & 1) * 8 + (lane & 7);
    int b_col = ((lane >> 3) & 1) * 8;

    float acc[2][8][4] = {};

    gemm_load_stage(dynh,         Ain, W, m0, n0, 0,  tid);
    gemm_load_stage(dynh + 18432, Ain, W, m0, n0, 64, tid);

    for (int kt = 0; kt < 16; kt++) {
        if (kt + 1 < 16) cp_wait<1>(); else cp_wait<0>();
        __syncthreads();
        if (kt + 2 < 16)
            gemm_load_stage(dynh + ((kt + 2) % 3) * 18432, Ain, W, m0, n0, (kt + 2) * 64, tid);

        __half* AsS = dynh + (kt % 3) * 18432;
        __half* WsS = AsS + 9216;

        #pragma unroll
        for (int kc = 0; kc < 4; kc++) {
            unsigned af[2][4];
            #pragma unroll
            for (int mi = 0; mi < 2; mi++) {
                int r = mw * 32 + mi * 16 + a_row;
                ldm_x4(af[mi], sptr(&AsS[r * 72 + kc * 16 + a_col]));
            }
            #pragma unroll
            for (int jb = 0; jb < 4; jb++) {
                unsigned rr[4];
                int n = nw * 64 + jb * 16 + b_row;
                ldm_x4(rr, sptr(&WsS[n * 72 + kc * 16 + b_col]));
                mma16(acc[0][2 * jb],     af[0], rr);
                mma16(acc[1][2 * jb],     af[1], rr);
                mma16(acc[0][2 * jb + 1], af[0], rr + 2);
                mma16(acc[1][2 * jb + 1], af[1], rr + 2);
            }
        }
    }

    #pragma unroll
    for (int mi = 0; mi < 2; mi++) {
        int r = m0 + mw * 32 + mi * 16 + gid;
        #pragma unroll
        for (int j = 0; j < 8; j++) {
            int c = n0 + nw * 64 + j * 8 + tig * 2;
            float b0v = bias[c], b1v = bias[c + 1];
            float2 v0 = { acc[mi][j][0] + b0v, acc[mi][j][1] + b1v };
            float2 v1 = { acc[mi][j][2] + b0v, acc[mi][j][3] + b1v };
            if (mode == 0) { v0.x *= QSCALE; v0.y *= QSCALE; v1.x *= QSCALE; v1.y *= QSCALE; }
            if (mode == 3) {
                *(float2*)&C[(size_t)r * D_ + c] = v0;
                *(float2*)&C[(size_t)(r + 8) * D_ + c] = v1;
            } else if (mode == 2) {
                int h = c >> 6, d = c & 63;
                int t = r >> 1, b = r & 1;
                size_t base = ((size_t)(b * H_ + h) * HD + d) * T_;
                g_vt[base + t]      = __float2half(v0.x);
                g_vt[base + T_ + t] = __float2half(v0.y);
                int t8 = t + 4;
                g_vt[base + t8]      = __float2half(v1.x);
                g_vt[base + T_ + t8] = __float2half(v1.y);
            } else {
                __half* outp = (mode == 0) ? g_qh : g_kh;
                int h = c >> 6, d = c & 63;
                int t = r >> 1, b = r & 1;
                __half2 h0 = __floats2half2_rn(v0.x, v0.y);
                __half2 h1 = __floats2half2_rn(v1.x, v1.y);
                *(__half2*)&outp[((size_t)(b * H_ + h) * T_ + t) * HD + d] = h0;
                *(__half2*)&outp[((size_t)(b * H_ + h) * T_ + t + 4) * HD + d] = h1;
            }
        }
    }
}

// ---------------------------------------------------------------------------
// Flash attention: deferred-PV pipeline + packed f32x2 softmax (fixed).
// 4-stage K/V ring (prefetch dist 2), one sync/iter, 2 CTAs/SM.
// ---------------------------------------------------------------------------
__device__ __forceinline__ void flash_load_kv(
    __half* Kst, __half* Vst, const __half* kb, const __half* vtb, int s0, int tid)
{
    #pragma unroll
    for (int p = 0; p < 2; p++) {
        int i = p * 256 + tid;
        int row = i >> 3, c = (i & 7) * 8;
        cp16(Kst + row * 72 + c, kb  + (size_t)(s0 + row) * HD + c);
        cp16(Vst + row * 72 + c, vtb + (size_t)row * T_ + s0 + c);
    }
    CP_COMMIT();
}

__global__ __launch_bounds__(256, 2) void flash_fp16()
{
    int bh = blockIdx.y;
    int tt = (int)(gridDim.x - 1 - blockIdx.x);
    int t0 = tt * 128;
    int tid = threadIdx.x, lane = tid & 31, w = tid >> 5;
    int gid = lane >> 2, tig = lane & 3;
    int lrow = w * 16 + gid;

    int a_row = lane & 15;
    int a_col = ((lane >> 4) & 1) * 8;
    int b_row = ((lane >> 4) & 1) * 8 + (lane & 7);
    int b_col = ((lane >> 3) & 1) * 8;

    const __half* qb  = g_qh + (size_t)bh * T_ * HD;
    const __half* kb  = g_kh + (size_t)bh * T_ * HD;
    const __half* vtb = g_vt + (size_t)bh * HD * T_;

    {
        #pragma unroll
        for (int p = 0; p < 4; p++) {
            int i = p * 256 + tid;
            int row = i >> 3, c = (i & 7) * 8;
            uint4 v = *(const uint4*)(qb + (size_t)(t0 + row) * HD + c);
            *(uint4*)(dynh + row * 72 + c) = v;
        }
    }
    __syncthreads();
    unsigned qf[4][4];
    {
        int r = w * 16 + a_row;
        #pragma unroll
        for (int kk = 0; kk < 4; kk++)
            ldm_x4(qf[kk], sptr(&dynh[r * 72 + kk * 16 + a_col]));
    }
    __syncthreads();

    float acc_o[8][4] = {};
    float m0v = -1e30f, m1v = -1e30f, l0 = 0.0f, l1 = 0.0f;

    int tt64 = tt * 2 + (lrow >= 64 ? 1 : 0);
    int rloc = lrow & 63;
    int nst = 2 * tt + 2;

    flash_load_kv(dynh, dynh + 4608, kb, vtb, 0, tid);
    if (nst > 1) flash_load_kv(dynh + 9216, dynh + 9216 + 4608, kb, vtb, 64, tid);

    unsigned p0[8], p1[8];

    for (int st = 0; st < nst; st++) {
        if (st + 1 < nst) cp_wait<1>(); else cp_wait<0>();
        __syncthreads();
        if (st + 2 < nst) {
            __half* Kn = dynh + ((st + 2) & 3) * 9216;
            flash_load_kv(Kn, Kn + 4608, kb, vtb, (st + 2) * 64, tid);
        }

        __half* Ks = dynh + (st & 3) * 9216;

        // ---- QK(st)
        float sc[8][4] = {};
        #pragma unroll
        for (int kk = 0; kk < 4; kk++) {
            #pragma unroll
            for (int jb = 0; jb < 4; jb++) {
                unsigned rr[4];
                int n = jb * 16 + b_row;
                ldm_x4(rr, sptr(&Ks[n * 72 + kk * 16 + b_col]));
                mma16(sc[2 * jb],     qf[kk], rr);
                mma16(sc[2 * jb + 1], qf[kk], rr + 2);
            }
        }

        // ---- deferred PV(st-1) (overlaps softmax below)
        if (st > 0) {
            __half* Vp = dynh + ((st - 1) & 3) * 9216 + 4608;
            #pragma unroll
            for (int kk = 0; kk < 4; kk++) {
                unsigned af[4] = { p0[2 * kk], p1[2 * kk], p0[2 * kk + 1], p1[2 * kk + 1] };
                #pragma unroll
                for (int jb = 0; jb < 4; jb++) {
                    unsigned rr[4];
                    int n = jb * 16 + b_row;
                    ldm_x4(rr, sptr(&Vp[n * 72 + kk * 16 + b_col]));
                    mma16(acc_o[2 * jb],     af, rr);
                    mma16(acc_o[2 * jb + 1], af, rr + 2);
                }
            }
        }

        // ---- causal mask
        if (st >= 2 * tt) {
            int s0 = st * 64;
            int rg0 = t0 + lrow, rg1 = rg0 + 8;
            #pragma unroll
            for (int j = 0; j < 8; j++) {
                int cg = s0 + j * 8 + 2 * tig;
                if (cg     > rg0) sc[j][0] = -1e30f;
                if (cg + 1 > rg0) sc[j][1] = -1e30f;
                if (cg     > rg1) sc[j][2] = -1e30f;
                if (cg + 1 > rg1) sc[j][3] = -1e30f;
            }
        }

        // ---- online softmax (packed f32x2 poly)
        float mx0 = -1e30f, mx1 = -1e30f;
        #pragma unroll
        for (int j = 0; j < 8; j++) {
            mx0 = fmaxf(mx0, fmaxf(sc[j][0], sc[j][1]));
            mx1 = fmaxf(mx1, fmaxf(sc[j][2], sc[j][3]));
        }
        mx0 = fmaxf(mx0, __shfl_xor_sync(0xffffffffu, mx0, 1));
        mx0 = fmaxf(mx0, __shfl_xor_sync(0xffffffffu, mx0, 2));
        mx1 = fmaxf(mx1, __shfl_xor_sync(0xffffffffu, mx1, 1));
        mx1 = fmaxf(mx1, __shfl_xor_sync(0xffffffffu, mx1, 2));

        float mn0 = fmaxf(m0v, mx0), mn1 = fmaxf(m1v, mx1);
        float fac0 = fmaxf(m0v - mn0, -100.0f);
        float fac1 = fmaxf(m1v - mn1, -100.0f);
        exp2_2(fac0, fac1);

        float s0v = 0.0f, s1v = 0.0f;
        #pragma unroll
        for (int j = 0; j < 8; j++) {
            float a0 = fmaxf(sc[j][0] - mn0, -100.0f);
            float a1 = fmaxf(sc[j][1] - mn0, -100.0f);
            float a2 = fmaxf(sc[j][2] - mn1, -100.0f);
            float a3 = fmaxf(sc[j][3] - mn1, -100.0f);
            exp2_2(a0, a1);
            exp2_2(a2, a3);
            sc[j][0] = a0; sc[j][1] = a1; sc[j][2] = a2; sc[j][3] = a3;
            s0v += a0 + a1;
            s1v += a2 + a3;
        }
        s0v += __shfl_xor_sync(0xffffffffu, s0v, 1);
        s0v += __shfl_xor_sync(0xffffffffu, s0v, 2);
        s1v += __shfl_xor_sync(0xffffffffu, s1v, 1);
        s1v += __shfl_xor_sync(0xffffffffu, s1v, 2);

        l0 = l0 * fac0 + s0v;
        l1 = l1 * fac1 + s1v;
        m0v = mn0; m1v = mn1;

        // ---- rescale acc (after PV(st-1))
        #pragma unroll
        for (int j = 0; j < 8; j++) {
            acc_o[j][0] *= fac0; acc_o[j][1] *= fac0;
            acc_o[j][2] *= fac1; acc_o[j][3] *= fac1;
        }

        // ---- pack P(st)
        #pragma unroll
        for (int j = 0; j < 8; j++) {
            __half2 a = __floats2half2_rn(sc[j][0], sc[j][1]);
            __half2 b2 = __floats2half2_rn(sc[j][2], sc[j][3]);
            p0[j] = *(unsigned*)&a;
            p1[j] = *(unsigned*)&b2;
        }

        __half* tb = g_e + ((size_t)(bh * NT + tt64) * NT + st) * 4096;
        #pragma unroll
        for (int j = 0; j < 8; j++) {
            int c = j * 8 + 2 * tig;
            *(unsigned*)(tb + rloc * 64 + c)       = p0[j];
            *(unsigned*)(tb + (rloc + 8) * 64 + c) = p1[j];
        }
        if (tig == 0) {
            g_mloc[((size_t)bh * T_ + t0 + lrow) * NT + st]     = mn0;
            g_mloc[((size_t)bh * T_ + t0 + lrow + 8) * NT + st] = mn1;
        }
    }

    // ---- tail PV(nst-1)
    {
        __half* Vp = dynh + ((nst - 1) & 3) * 9216 + 4608;
        #pragma unroll
        for (int kk = 0; kk < 4; kk++) {
            unsigned af[4] = { p0[2 * kk], p1[2 * kk], p0[2 * kk + 1], p1[2 * kk + 1] };
            #pragma unroll
            for (int jb = 0; jb < 4; jb++) {
                unsigned rr[4];
                int n = jb * 16 + b_row;
                ldm_x4(rr, sptr(&Vp[n * 72 + kk * 16 + b_col]));
                mma16(acc_o[2 * jb],     af, rr);
                mma16(acc_o[2 * jb + 1], af, rr + 2);
            }
        }
    }

    int b = bh >> 4, h = bh & 15;
    float inv0 = 1.0f / l0, inv1 = 1.0f / l1;
    #pragma unroll
    for (int j = 0; j < 8; j++) {
        int d = h * 64 + j * 8 + 2 * tig;
        __half2 h0 = __floats2half2_rn(acc_o[j][0] * inv0, acc_o[j][1] * inv0);
        __half2 h1 = __floats2half2_rn(acc_o[j][2] * inv1, acc_o[j][3] * inv1);
        *(__half2*)&g_attn[((size_t)(t0 + lrow) * B_ + b) * D_ + d] = h0;
        *(__half2*)&g_attn[((size_t)(t0 + lrow + 8) * B_ + b) * D_ + d] = h1;
    }
    if (tig == 0) {
        g_lse[(size_t)bh * T_ + t0 + lrow]     = m0v + log2f(l0);
        g_lse[(size_t)bh * T_ + t0 + lrow + 8] = m1v + log2f(l1);
    }
}

// ---------------------------------------------------------------------------
// Avg weights (unchanged; upper triangle done by zfill_kernel).
// ---------------------------------------------------------------------------
__global__ __launch_bounds__(256) void avg_kernel(float* __restrict__ out)
{
    __shared__ float sfac[16][64];
    int st = blockIdx.x, tt = blockIdx.y, b = blockIdx.z;
    if (st > tt) return;

    int t0 = tt * 64, s0 = st * 64;
    int tid = threadIdx.x;
    int row = tid >> 2, cseg = (tid & 3) * 16;

    float* dst = out + (size_t)ROWS * D_ + (size_t)b * T_ * T_;
    float4* pout = (float4*)(dst + (size_t)(t0 + row) * T_ + s0 + cseg);

    #pragma unroll
    for (int q = 0; q < 4; q++) {
        int idx = tid * 4 + q;
        int h = idx >> 6, r = idx & 63;
        size_t rowg = (size_t)(b * H_ + h) * T_ + t0 + r;
        sfac[h][r] = fast_exp2(g_mloc[rowg * NT + st] - g_lse[rowg]);
    }
    __syncthreads();

    float acc[16] = {};
    const __half* ebase = g_e + ((size_t)(b * H_) * NT + tt) * NT * 4096
                          + (size_t)st * 4096 + row * 64 + cseg;
    #pragma unroll 4
    for (int h = 0; h < H_; h++) {
        float fac = sfac[h][row];
        const uint4* ep = (const uint4*)(ebase + (size_t)h * NT * NT * 4096);
        #pragma unroll
        for (int q2 = 0; q2 < 2; q2++) {
            uint4 u = ep[q2];
            const __half2* hp = (const __half2*)&u;
            #pragma unroll
            for (int i = 0; i < 4; i++) {
                float2 f = __half22float2(hp[i]);
                acc[q2 * 8 + i * 2]     += fac * f.x;
                acc[q2 * 8 + i * 2 + 1] += fac * f.y;
            }
        }
    }
    const float invH = 1.0f / (float)H_;
    #pragma unroll
    for (int q2 = 0; q2 < 4; q2++) {
        float4 v = { acc[q2 * 4] * invH, acc[q2 * 4 + 1] * invH,
                     acc[q2 * 4 + 2] * invH, acc[q2 * 4 + 3] * invH };
        pout[q2] = v;
    }
}

// ---------------------------------------------------------------------------
extern "C" void kernel_launch(void* const* d_in, const int* in_sizes, int n_in,
                              void* d_out, int out_size)
{
    const float* query = (const float*)d_in[0];
    const float* qw = (const float*)d_in[1];
    const float* qb = (const float*)d_in[2];
    const float* kw = (const float*)d_in[3];
    const float* kb = (const float*)d_in[4];
    const float* vw = (const float*)d_in[5];
    const float* vb = (const float*)d_in[6];
    const float* ow = (const float*)d_in[7];
    const float* ob = (const float*)d_in[8];
    float* out = (float*)d_out;

    const int SM_G = 110592;
    const int SM_F = 73728;
    cudaFuncSetAttribute(gemm_fp16, cudaFuncAttributeMaxDynamicSharedMemorySize, SM_G);
    cudaFuncSetAttribute(flash_fp16, cudaFuncAttributeMaxDynamicSharedMemorySize, SM_F);

    static cudaStream_t s2 = nullptr;
    static cudaEvent_t ev1 = nullptr, ev2 = nullptr, evFork = nullptr, evJoin = nullptr;
    static bool init_ok = false;
    static bool init_tried = false;
    if (!init_tried) {
        init_tried = true;
        init_ok = (cudaStreamCreateWithFlags(&s2, cudaStreamNonBlocking) == cudaSuccess)
               && (cudaEventCreateWithFlags(&ev1, cudaEventDisableTiming) == cudaSuccess)
               && (cudaEventCreateWithFlags(&ev2, cudaEventDisableTiming) == cudaSuccess)
               && (cudaEventCreateWithFlags(&evFork, cudaEventDisableTiming) == cudaSuccess)
               && (cudaEventCreateWithFlags(&evJoin, cudaEventDisableTiming) == cudaSuccess);
    }

    const size_t NX = (size_t)ROWS * D_ / 4;
    const size_t NW = (size_t)D_ * D_ / 4;
    int prep_main_blocks = (int)((NX + 3 * NW) / 256);
    int prep_wo_blocks   = (int)(NW / 256);

    if (init_ok) {
        prep_main<<<prep_main_blocks, 256>>>(query, qw, kw, vw);
        cudaEventRecord(ev1, 0);
        cudaStreamWaitEvent(s2, ev1, 0);
        prep_wo<<<prep_wo_blocks, 256, 0, s2>>>(ow);
        zfill_kernel<<<dim3(NT, NT, B_), 256, 0, s2>>>(out);
        cudaEventRecord(ev2, s2);

        gemm_fp16<<<dim3(8, 32, 3), 256, SM_G>>>(qb, kb, vb, nullptr, -1);
        flash_fp16<<<dim3(NQT, BH), 256, SM_F>>>();

        cudaEventRecord(evFork, 0);
        cudaStreamWaitEvent(s2, evFork, 0);
        avg_kernel<<<dim3(NT, NT, B_), 256, 0, s2>>>(out);
        cudaStreamWaitEvent(0, ev2, 0);
        gemm_fp16<<<dim3(8, 32, 1), 256, SM_G>>>(ob, ob, ob, out, 3);
        cudaEventRecord(evJoin, s2);
        cudaStreamWaitEvent(0, evJoin, 0);
    } else {
        prep_main<<<prep_main_blocks, 256>>>(query, qw, kw, vw);
        prep_wo<<<prep_wo_blocks, 256>>>(ow);
        zfill_kernel<<<dim3(NT, NT, B_), 256>>>(out);
        gemm_fp16<<<dim3(8, 32, 3), 256, SM_G>>>(qb, kb, vb, nullptr, -1);
        flash_fp16<<<dim3(NQT, BH), 256, SM_F>>>();
        avg_kernel<<<dim3(NT, NT, B_), 256>>>(out);
        gemm_fp16<<<dim3(8, 32, 1), 256, SM_G>>>(ob, ob, ob, out, 3);
    }
}